// round 16
// baseline (speedup 1.0000x reference)
#include <cuda_runtime.h>
#include <cuda_fp16.h>
#include <cstdint>

// ---------------------------------------------------------------------------
// W4A16 grouped GEMM: out[32,28672] = x[32,8192] @ dequant(qweight) + bias
//   qweight int32 [K/8, N]: 8 int4 nibbles per word along K, zero-point 8
//   x / scales / bias fp16-origin delivered as f32; output f32.
//
// R15: KC=128 (one scale-group per chunk), NBUF=2, one cp.async wait + one
// __syncthreads per chunk -> half the sync windows of R14, double the
// independent work per window (8 k16 steps). Pipeline per iter:
//   wait_group 0 (chunk ci landed) -> sync (buf^1 free) ->
//   stage ci+1 into buf^1 -> compute ci      (cp.async overlaps compute)
// Single wave kept: grid (224,4) = 896 CTAs, 6/SM (SMEM 34.5 KB -> 6).
// Everything else unchanged from R14 (best: 78.6us):
//   - pre-kernel x f32->f16 into g_xf16 (512 KB, L2-resident)
//   - 128 thr, NT=128, W/NT=4/128, split-K x4, fused last-CTA reduction
//   - mma.sync.m16n8k16 + ldmatrix; dequant byte_perm + magic-bias +
//     exact HSUB2{1032,1152}/HMUL2{s,s/16} (one fp16 rounding per weight)
// ---------------------------------------------------------------------------

static constexpr int MDIM    = 32;
static constexpr int KDIM    = 8192;
static constexpr int NDIM    = 28672;
static constexpr int NT      = 128;                 // n per CTA tile
static constexpr int KC      = 128;                 // k per chunk (= group)
static constexpr int KSPLIT  = 4;
static constexpr int CPS     = KDIM / KC / KSPLIT;  // 16 chunks per split
static constexpr int NTILES  = NDIM / NT;           // 224
static constexpr int THREADS = 128;
static constexpr int XSTRIDE = 272;                 // bytes per x row (256+16 pad)

__device__ __half g_xf16[MDIM * KDIM];              // 512 KB x in fp16
__device__ float  g_scratch[KSPLIT * MDIM * NDIM];  // 14.7 MB partials
__device__ int    g_cnt[NTILES];                    // zero-init; reset in-kernel

// --------------------------- PTX helpers -----------------------------------

__device__ __forceinline__ uint32_t smem_u32(const void* p) {
    uint32_t a;
    asm("{ .reg .u64 t; cvta.to.shared.u64 t, %1; cvt.u32.u64 %0, t; }"
        : "=r"(a) : "l"(p));
    return a;
}

__device__ __forceinline__ void cp16(uint32_t dst, const void* src) {
    asm volatile("cp.async.cg.shared.global [%0], [%1], 16;"
                 :: "r"(dst), "l"(src) : "memory");
}
__device__ __forceinline__ void cp4(uint32_t dst, const void* src) {
    asm volatile("cp.async.ca.shared.global [%0], [%1], 4;"
                 :: "r"(dst), "l"(src) : "memory");
}
__device__ __forceinline__ void cp_commit() {
    asm volatile("cp.async.commit_group;" ::: "memory");
}
__device__ __forceinline__ void cp_wait0() {
    asm volatile("cp.async.wait_group 0;" ::: "memory");
}

__device__ __forceinline__ void ldmatrix_x4(uint32_t* r, uint32_t addr) {
    asm volatile(
        "ldmatrix.sync.aligned.m8n8.x4.shared.b16 {%0,%1,%2,%3}, [%4];"
        : "=r"(r[0]), "=r"(r[1]), "=r"(r[2]), "=r"(r[3]) : "r"(addr));
}

__device__ __forceinline__ void mma_16816(float* c, const uint32_t* a,
                                          uint32_t b0, uint32_t b1) {
    asm volatile(
        "mma.sync.aligned.m16n8k16.row.col.f32.f16.f16.f32 "
        "{%0,%1,%2,%3}, {%4,%5,%6,%7}, {%8,%9}, {%0,%1,%2,%3};"
        : "+f"(c[0]), "+f"(c[1]), "+f"(c[2]), "+f"(c[3])
        : "r"(a[0]), "r"(a[1]), "r"(a[2]), "r"(a[3]), "r"(b0), "r"(b1));
}

// --------------------------- dequant ---------------------------------------
// Byte t of word w holds (k=2t lo-nibble, k=2t+1 hi-nibble). byte_perm
// replicates byte t into bytes 0,2; mask+OR builds {1024+n_lo, 1024+16*n_hi};
// exact HSUB2 {1032,1152} then HMUL2 {s, s/16} -> {(n_lo-8)s, (n_hi-8)s}.
__device__ __forceinline__ uint32_t dq_pair(uint32_t w, uint32_t sel, uint32_t mul2u) {
    const uint32_t SUBC = 0x64806408u;  // half2 {1032, 1152}
    uint32_t v = __byte_perm(w, 0, sel);
    uint32_t p = (v & 0x00F0000Fu) | 0x64006400u;
    __half2 h = __hmul2(__hsub2(*reinterpret_cast<__half2*>(&p),
                                *reinterpret_cast<const __half2*>(&SUBC)),
                        *reinterpret_cast<__half2*>(&mul2u));
    return *reinterpret_cast<uint32_t*>(&h);
}

// --------------------------- x convert pre-kernel ---------------------------

__global__ void __launch_bounds__(256)
x_convert_kernel(const float* __restrict__ x) {
    const int i = (blockIdx.x * 256 + threadIdx.x) * 4;
    float4 v = *reinterpret_cast<const float4*>(x + i);
    __half2 h0 = __floats2half2_rn(v.x, v.y);
    __half2 h1 = __floats2half2_rn(v.z, v.w);
    uint2 u = { *reinterpret_cast<uint32_t*>(&h0), *reinterpret_cast<uint32_t*>(&h1) };
    *reinterpret_cast<uint2*>(&g_xf16[i]) = u;
}

// --------------------------- main kernel ------------------------------------

__global__ void __launch_bounds__(THREADS)
w4a16_partial_kernel(const uint32_t* __restrict__ qweight,
                     const float* __restrict__ scales,
                     const float* __restrict__ bias,
                     float* __restrict__ out) {
    __shared__ uint32_t s_qw[2][16 * 128];                    // 16 KB
    __shared__ __align__(16) uint8_t s_x[2][32 * XSTRIDE];    // 17 KB
    __shared__ float s_sc[2][128];                            // 1 KB
    __shared__ int s_last;

    const int tid  = threadIdx.x;
    const int lane = tid & 31;
    const int wid  = tid >> 5;
    const int tile = blockIdx.x;
    const int n0   = tile * NT;
    const int ks   = blockIdx.y;
    const int c0   = ks * CPS;
    const int t4   = lane & 3;
    const uint32_t sel = 0x4040u + (uint32_t)t4 * 0x0101u;

    int nl[4];
#pragma unroll
    for (int j = 0; j < 4; ++j) nl[j] = wid * 32 + (lane >> 2) + 8 * j;

    const __half one16 = __ushort_as_half(0x2C00);   // 1/16

    // per-thread cp.async sources (chunk offset added per stage)
    //   qweight chunk: 16 rows x 128 words; thread -> row tid>>3, 16 words
    //   x chunk:       32 rows x 128 halfs; thread -> row tid>>2, 32 halfs
    const uint32_t* qsrc0 = qweight + (tid >> 3) * NDIM + n0 + (tid & 7) * 16;
    const __half*   xsrc0 = g_xf16 + (tid >> 2) * KDIM + (tid & 3) * 32;
    const float*    ssrc0 = scales + n0 + tid;

    // per-thread cp.async SMEM destinations (buf 0)
    const uint32_t qdst0 = smem_u32(&s_qw[0][0]) + ((tid >> 3) * 128 + (tid & 7) * 16) * 4;
    const uint32_t xdst0 = smem_u32(&s_x[0][0]) + (tid >> 2) * XSTRIDE + (tid & 3) * 64;
    const uint32_t sdst0 = smem_u32(&s_sc[0][0]) + tid * 4;

    const uint32_t xm_base = smem_u32(&s_x[0][0]) +
                             (uint32_t)(lane & 15) * XSTRIDE + (uint32_t)(lane >> 4) * 16;

    float acc[2][4][4];
#pragma unroll
    for (int mt = 0; mt < 2; ++mt)
#pragma unroll
        for (int j = 0; j < 4; ++j)
#pragma unroll
            for (int r = 0; r < 4; ++r) acc[mt][j][r] = 0.0f;

    // stage(chunk c, buffer b): 9 cp.asyncs + commit
    auto stage = [&](int c, int b) {
        const uint32_t* qs = qsrc0 + c * 16 * NDIM;
        uint32_t qd = qdst0 + b * (16 * 128 * 4);
        cp16(qd,      qs);
        cp16(qd + 16, qs + 4);
        cp16(qd + 32, qs + 8);
        cp16(qd + 48, qs + 12);
        const __half* xs = xsrc0 + c * 128;
        uint32_t xd = xdst0 + b * (32 * XSTRIDE);
        cp16(xd,      xs);
        cp16(xd + 16, xs + 8);
        cp16(xd + 32, xs + 16);
        cp16(xd + 48, xs + 24);
        cp4(sdst0 + b * (128 * 4), ssrc0 + c * NDIM);
        cp_commit();
    };

    // prologue: chunk 0 in flight
    stage(c0, 0);

    int buf = 0;
    for (int ci = 0; ci < CPS; ++ci) {
        cp_wait0();          // chunk ci landed
        __syncthreads();     // visible to all; buf^1 free (ci-1 compute done)

        if (ci + 1 < CPS) stage(c0 + ci + 1, buf ^ 1);   // overlaps compute

        // per-n-column multipliers {s, s/16} — one group per chunk
        uint32_t mul2[4];
#pragma unroll
        for (int j = 0; j < 4; ++j) {
            __half s = __float2half(s_sc[buf][nl[j]]);
            __half2 m = __halves2half2(s, __hmul(s, one16));
            mul2[j] = *reinterpret_cast<uint32_t*>(&m);
        }
        const uint32_t* qs = &s_qw[buf][0];
        const uint32_t xb = xm_base + (uint32_t)buf * (32 * XSTRIDE);

#pragma unroll
        for (int s4 = 0; s4 < 8; ++s4) {                  // 8 k16 steps
            uint32_t a0[4], a1[4];
            ldmatrix_x4(a0, xb + s4 * 32);                // m rows 0-15
            ldmatrix_x4(a1, xb + s4 * 32 + 16 * XSTRIDE); // m rows 16-31
#pragma unroll
            for (int j = 0; j < 4; ++j) {
                uint32_t w0 = qs[(2 * s4)     * 128 + nl[j]];
                uint32_t w1 = qs[(2 * s4 + 1) * 128 + nl[j]];
                uint32_t b0 = dq_pair(w0, sel, mul2[j]);  // k = 2t, 2t+1
                uint32_t b1 = dq_pair(w1, sel, mul2[j]);  // k = 2t+8, 2t+9
                mma_16816(acc[0][j], a0, b0, b1);
                mma_16816(acc[1][j], a1, b0, b1);
            }
        }
        buf ^= 1;
    }

    // partial epilogue: raw f32 sums to scratch[ks][m][n]
    float* sp = g_scratch + ks * (MDIM * NDIM);
#pragma unroll
    for (int j = 0; j < 4; ++j) {
        const int n = n0 + wid * 32 + j * 8 + 2 * t4;
#pragma unroll
        for (int mt = 0; mt < 2; ++mt) {
            const int m0 = mt * 16 + (lane >> 2);
            float2 v01 = { acc[mt][j][0], acc[mt][j][1] };
            float2 v23 = { acc[mt][j][2], acc[mt][j][3] };
            *reinterpret_cast<float2*>(sp + m0 * NDIM + n)       = v01;
            *reinterpret_cast<float2*>(sp + (m0 + 8) * NDIM + n) = v23;
        }
    }

    // ---- fused reduction: last CTA of this tile sums the 4 partials --------
    __threadfence();
    if (tid == 0) {
        int old = atomicAdd(&g_cnt[tile], 1);
        s_last = (old == KSPLIT - 1);
    }
    __syncthreads();
    if (!s_last) return;

    if (tid == 0) g_cnt[tile] = 0;   // reset for next launch / graph replay
    __threadfence();                 // acquire: counter observation -> loads

    const int n = n0 + tid;          // 128 threads : 128 columns
    const __half hb = __float2half(bias[n]);
    const float* sp0 = g_scratch + n;
#pragma unroll 4
    for (int m = 0; m < MDIM; ++m) {
        float s = 0.0f;
#pragma unroll
        for (int k = 0; k < KSPLIT; ++k)
            s += sp0[(k * MDIM + m) * NDIM];
        out[m * NDIM + n] = __half2float(__hadd(__float2half(s), hb));
    }
}

// --------------------------- launch ------------------------------------------

extern "C" void kernel_launch(void* const* d_in, const int* in_sizes, int n_in,
                              void* d_out, int out_size) {
    (void)out_size;
    const float*    x    = nullptr;   // 262144
    const uint32_t* qw   = nullptr;   // 29360128
    const float*    sc   = nullptr;   // 1835008
    const float*    bias = nullptr;   // 28672
    for (int i = 0; i < n_in; ++i) {
        switch (in_sizes[i]) {
            case MDIM * KDIM:            x    = (const float*)d_in[i];    break;
            case (KDIM / 8) * NDIM:      qw   = (const uint32_t*)d_in[i]; break;
            case (KDIM / 128) * NDIM:    sc   = (const float*)d_in[i];    break;
            case NDIM:                   bias = (const float*)d_in[i];    break;
            default: break;
        }
    }
    float* out = (float*)d_out;

    x_convert_kernel<<<MDIM * KDIM / (256 * 4), 256>>>(x);

    dim3 grid(NTILES, KSPLIT);   // (224, 4) = 896 CTAs -> single wave
    w4a16_partial_kernel<<<grid, THREADS>>>(qw, sc, bias, out);
}